// round 11
// baseline (speedup 1.0000x reference)
#include <cuda_runtime.h>
#include <cstdint>

// TCNN_INR via mma.sync tf32 HMMA. 512-thread persistent CTAs (16 warps,
// 4/SMSP for latency hiding), <=128 regs/thread. Warp (mg=warp>>3, nw=warp&7)
// owns M-tiles mg*4..+4 and N-cols nw*16..+16. Weights staged once per CTA in
// fragment layout; H1 relayed between layers in fragment-native layout
// (one STS.128/LDS.128 per fragment, conflict-free).

#define PRIME_Y   2654435761u
#define HASH_MASK 0xFFFFFu

__constant__ float    c_scale[12] = {15.0f, 23.0f, 35.0f, 53.0f, 80.0f, 120.5f,
                                     181.25f, 272.375f, 409.0625f, 614.09375f,
                                     921.640625f, 1382.9609375f};
__constant__ unsigned c_res[12]   = {16u, 24u, 36u, 54u, 81u, 122u,
                                     183u, 274u, 411u, 616u, 923u, 1384u};

// k-interleave permutation within 8-groups for E storage: [0,4,1,5,2,6,3,7]
__device__ __forceinline__ int pcol(int k) {
    int j = k & 7;
    return (k & ~7) | ((j < 4) ? (j << 1) : (((j - 4) << 1) | 1));
}

__device__ __forceinline__ uint32_t f2tf32(float f) {
    uint32_t b;
    asm("cvt.rna.tf32.f32 %0, %1;" : "=r"(b) : "f"(f));
    return b;
}

__device__ __forceinline__ void mma8(float& d0, float& d1, float& d2, float& d3,
                                     uint32_t a0, uint32_t a1, uint32_t a2, uint32_t a3,
                                     uint32_t b0, uint32_t b1) {
    asm volatile("mma.sync.aligned.m16n8k8.row.col.f32.tf32.tf32.f32 "
                 "{%0,%1,%2,%3}, {%4,%5,%6,%7}, {%8,%9}, {%0,%1,%2,%3};"
                 : "+f"(d0), "+f"(d1), "+f"(d2), "+f"(d3)
                 : "r"(a0), "r"(a1), "r"(a2), "r"(a3), "r"(b0), "r"(b1));
}

// SMEM float offsets
#define E_STRIDE  50
#define E_OFF     0
#define W1F_OFF   (E_OFF   + 128 * E_STRIDE)  // 6400
#define W2F_OFF   (W1F_OFF + 6144)            // 12544
#define H1F_OFF   (W2F_OFF + 16384)           // 28928
#define P0_OFF    (H1F_OFF + 16384)           // 45312
#define P1_OFF    (P0_OFF  + 512)             // 45824
#define W3_OFF    (P1_OFF  + 512)             // 46336
#define SMEM_FLOATS (W3_OFF + 128)            // 46464
#define SMEM_BYTES  (SMEM_FLOATS * 4)         // 185856

#define NUM_TILES 8

__global__ void __launch_bounds__(512, 1)
tcnn_hmma4_kernel(const float* __restrict__ table,
                  const float* __restrict__ w1,
                  const float* __restrict__ w2,
                  const float* __restrict__ w3,
                  float* __restrict__ out)
{
    extern __shared__ float sm[];
    float*    E    = sm + E_OFF;
    uint32_t* Eu   = (uint32_t*)E;
    uint32_t* W1f  = (uint32_t*)(sm + W1F_OFF);
    uint32_t* W2f  = (uint32_t*)(sm + W2F_OFF);
    uint32_t* H1f  = (uint32_t*)(sm + H1F_OFF);
    float*    P0   = sm + P0_OFF;     // [128 rows][nw 0..3]
    float*    P1   = sm + P1_OFF;     // [128 rows][nw 4..7]
    float*    w3s  = sm + W3_OFF;

    const int tid  = threadIdx.x;
    const int lane = tid & 31;
    const int warp = tid >> 5;
    const int g    = lane >> 2;   // groupID
    const int t    = lane & 3;    // threadID_in_group
    const int mg   = warp >> 3;   // M-group (0..1): M-tiles mg*4..+4
    const int nw   = warp & 7;    // N-slice (0..7): cols nw*16..+16

    // ---- Stage weights ONCE per CTA, in fragment layouts ----
    // W1f: idx = nw*768 + kt*128 + nt*64 + lane*2 + pair
    // b-pair = (w1[kt*8+t][n], w1[kt*8+t+4][n]) to match E's pcol storage
    #pragma unroll 2
    for (int idx = tid; idx < 6144; idx += 512) {
        int pair = idx & 1;
        int ln   = (idx >> 1) & 31;
        int nt   = (idx >> 6) & 1;
        int kt   = (idx >> 7) % 6;
        int nwi  = idx / 768;
        int gg = ln >> 2, tt = ln & 3;
        int k = kt * 8 + tt + pair * 4;
        int n = nwi * 16 + nt * 8 + gg;
        W1f[idx] = f2tf32(w1[k * 128 + n]);
    }
    // W2f: idx = nw*2048 + kt*128 + nt*64 + lane*2 + pair
    // b-pair = (w2[kt*8+2t][n], w2[kt*8+2t+1][n]) to match H1f packing
    #pragma unroll 4
    for (int idx = tid; idx < 16384; idx += 512) {
        int pair = idx & 1;
        int ln   = (idx >> 1) & 31;
        int nt   = (idx >> 6) & 1;
        int kt   = (idx >> 7) & 15;
        int nwi  = idx >> 11;
        int gg = ln >> 2, tt = ln & 3;
        int k = kt * 8 + 2 * tt + pair;
        int n = nwi * 16 + nt * 8 + gg;
        W2f[idx] = f2tf32(w2[k * 128 + n]);
    }
    if (tid < 128) w3s[tid] = w3[tid];

    // ---- Tile loop ----
    #pragma unroll 1
    for (int it = 0; it < NUM_TILES; it++) {
        const int tile = blockIdx.x * NUM_TILES + it;

        // ---- Hash encoding: 4 threads/pixel, 3 levels each -> E ----
        {
            const int   lp    = tid & 127;
            const int   lbase = (tid >> 7) * 3;
            const int   pix   = tile * 128 + lp;
            const float fx = (float)(pix & 1023) * (1.0f / 1023.0f);
            const float fy = (float)(pix >> 10)  * (1.0f / 1023.0f);
            uint32_t* Er = Eu + lp * E_STRIDE;

            #pragma unroll
            for (int li = 0; li < 3; li++) {
                const int      l   = lbase + li;
                const float    s   = c_scale[l];
                const unsigned res = c_res[l];
                float posx = fmaf(fx, s, 0.5f);
                float posy = fmaf(fy, s, 0.5f);
                float fpx = floorf(posx), fpy = floorf(posy);
                float wx = posx - fpx,    wy = posy - fpy;
                unsigned px0 = (unsigned)fpx, py0 = (unsigned)fpy;
                unsigned px1 = min(px0 + 1u, res - 1u);
                unsigned py1 = min(py0 + 1u, res - 1u);

                unsigned i00, i10, i01, i11;
                if (l < 11) {
                    i00 = px0 + py0 * res;  i10 = px1 + py0 * res;
                    i01 = px0 + py1 * res;  i11 = px1 + py1 * res;
                } else {
                    unsigned hy0 = py0 * PRIME_Y, hy1 = py1 * PRIME_Y;
                    i00 = (px0 ^ hy0) & HASH_MASK;  i10 = (px1 ^ hy0) & HASH_MASK;
                    i01 = (px0 ^ hy1) & HASH_MASK;  i11 = (px1 ^ hy1) & HASH_MASK;
                }

                const float4* tb = (const float4*)table + ((size_t)l << 20);
                float4 f00 = __ldg(tb + i00);
                float4 f10 = __ldg(tb + i10);
                float4 f01 = __ldg(tb + i01);
                float4 f11 = __ldg(tb + i11);

                float w00 = (1.0f - wx) * (1.0f - wy);
                float w10 = wx * (1.0f - wy);
                float w01 = (1.0f - wx) * wy;
                float w11 = wx * wy;

                int k0 = l * 4;
                Er[pcol(k0 + 0)] = f2tf32(f00.x*w00 + f10.x*w10 + f01.x*w01 + f11.x*w11);
                Er[pcol(k0 + 1)] = f2tf32(f00.y*w00 + f10.y*w10 + f01.y*w01 + f11.y*w11);
                Er[pcol(k0 + 2)] = f2tf32(f00.z*w00 + f10.z*w10 + f01.z*w01 + f11.z*w11);
                Er[pcol(k0 + 3)] = f2tf32(f00.w*w00 + f10.w*w10 + f01.w*w01 + f11.w*w11);
            }
        }
        __syncthreads();

        // ---- Layer 1: warp computes H1[mg*64..+64, nw*16..+16) ----
        {
            uint32_t Bf[2][6][2];
            #pragma unroll
            for (int nt = 0; nt < 2; nt++)
                #pragma unroll
                for (int kt = 0; kt < 6; kt++) {
                    uint2 v = *(const uint2*)(W1f + (((nw * 6 + kt) * 2 + nt) * 32 + lane) * 2);
                    Bf[nt][kt][0] = v.x;  Bf[nt][kt][1] = v.y;
                }

            float d[4][2][4];
            #pragma unroll
            for (int mi = 0; mi < 4; mi++)
                #pragma unroll
                for (int nt = 0; nt < 2; nt++)
                    d[mi][nt][0] = d[mi][nt][1] = d[mi][nt][2] = d[mi][nt][3] = 0.0f;

            #pragma unroll
            for (int kt = 0; kt < 6; kt++) {
                #pragma unroll
                for (int mi = 0; mi < 4; mi++) {
                    int mt = mg * 4 + mi;
                    float2 va = *(const float2*)(E + (mt*16 + g    ) * E_STRIDE + kt * 8 + 2 * t);
                    float2 vb = *(const float2*)(E + (mt*16 + g + 8) * E_STRIDE + kt * 8 + 2 * t);
                    uint32_t a0 = __float_as_uint(va.x), a1 = __float_as_uint(vb.x);
                    uint32_t a2 = __float_as_uint(va.y), a3 = __float_as_uint(vb.y);
                    #pragma unroll
                    for (int nt = 0; nt < 2; nt++)
                        mma8(d[mi][nt][0], d[mi][nt][1], d[mi][nt][2], d[mi][nt][3],
                             a0, a1, a2, a3, Bf[nt][kt][0], Bf[nt][kt][1]);
                }
            }

            // ReLU + tf32 -> H1f, one STS.128 per fragment, (d0,d2,d1,d3) packing.
            // Fragment (m-tile mt, consumer kt_c = nw*2 + nt).
            #pragma unroll
            for (int mi = 0; mi < 4; mi++) {
                #pragma unroll
                for (int nt = 0; nt < 2; nt++) {
                    int mt  = mg * 4 + mi;
                    int ktc = nw * 2 + nt;
                    uint4 v;
                    v.x = f2tf32(fmaxf(d[mi][nt][0], 0.0f));
                    v.y = f2tf32(fmaxf(d[mi][nt][2], 0.0f));
                    v.z = f2tf32(fmaxf(d[mi][nt][1], 0.0f));
                    v.w = f2tf32(fmaxf(d[mi][nt][3], 0.0f));
                    *(uint4*)(H1f + ((mt * 16 + ktc) * 32 + lane) * 4) = v;
                }
            }
        }
        __syncthreads();

        // ---- Layer 2 (+w3 fusion): warp computes H2[mg*64..+64, nw*16..+16) ----
        {
            uint32_t Bf[2][16][2];
            #pragma unroll
            for (int nt = 0; nt < 2; nt++)
                #pragma unroll
                for (int kt = 0; kt < 16; kt++) {
                    uint2 v = *(const uint2*)(W2f + (((nw * 16 + kt) * 2 + nt) * 32 + lane) * 2);
                    Bf[nt][kt][0] = v.x;  Bf[nt][kt][1] = v.y;
                }

            float d[4][2][4];
            #pragma unroll
            for (int mi = 0; mi < 4; mi++)
                #pragma unroll
                for (int nt = 0; nt < 2; nt++)
                    d[mi][nt][0] = d[mi][nt][1] = d[mi][nt][2] = d[mi][nt][3] = 0.0f;

            #pragma unroll
            for (int kt = 0; kt < 16; kt++) {
                #pragma unroll
                for (int mi = 0; mi < 4; mi++) {
                    int mt = mg * 4 + mi;
                    uint4 A = *(const uint4*)(H1f + ((mt * 16 + kt) * 32 + lane) * 4);
                    #pragma unroll
                    for (int nt = 0; nt < 2; nt++)
                        mma8(d[mi][nt][0], d[mi][nt][1], d[mi][nt][2], d[mi][nt][3],
                             A.x, A.y, A.z, A.w, Bf[nt][kt][0], Bf[nt][kt][1]);
                }
            }

            // Layer 3 partials over this warp's 16 cols
            float w3c[2][2];
            #pragma unroll
            for (int nt = 0; nt < 2; nt++) {
                w3c[nt][0] = w3s[nw * 16 + nt * 8 + 2 * t];
                w3c[nt][1] = w3s[nw * 16 + nt * 8 + 2 * t + 1];
            }
            #pragma unroll
            for (int mi = 0; mi < 4; mi++) {
                float p0 = 0.0f, p1 = 0.0f;
                #pragma unroll
                for (int nt = 0; nt < 2; nt++) {
                    p0 += fmaxf(d[mi][nt][0], 0.0f) * w3c[nt][0]
                        + fmaxf(d[mi][nt][1], 0.0f) * w3c[nt][1];
                    p1 += fmaxf(d[mi][nt][2], 0.0f) * w3c[nt][0]
                        + fmaxf(d[mi][nt][3], 0.0f) * w3c[nt][1];
                }
                p0 += __shfl_xor_sync(0xFFFFFFFFu, p0, 1);
                p0 += __shfl_xor_sync(0xFFFFFFFFu, p0, 2);
                p1 += __shfl_xor_sync(0xFFFFFFFFu, p1, 1);
                p1 += __shfl_xor_sync(0xFFFFFFFFu, p1, 2);
                if (t == 0) {
                    int   row0 = mg * 64 + mi * 16 + g;
                    float* Pb  = (nw < 4) ? P0 : P1;
                    int   c    = nw & 3;
                    Pb[(row0    ) * 4 + c] = p0;
                    Pb[(row0 + 8) * 4 + c] = p1;
                }
            }
        }
        __syncthreads();

        // ---- Cross-warp reduction (8 nw slices per row) + output ----
        if (tid < 128) {
            float4 a = *(const float4*)(P0 + tid * 4);
            float4 b = *(const float4*)(P1 + tid * 4);
            out[tile * 128 + tid] = (a.x + a.y + a.z + a.w) + (b.x + b.y + b.z + b.w);
        }
    }
}

extern "C" void kernel_launch(void* const* d_in, const int* in_sizes, int n_in,
                              void* d_out, int out_size)
{
    const float *table = nullptr, *w1 = nullptr, *w2 = nullptr, *w3 = nullptr;
    for (int i = 0; i < n_in; i++) {
        switch (in_sizes[i]) {
            case 50331648: table = (const float*)d_in[i]; break;
            case 6144:     w1    = (const float*)d_in[i]; break;
            case 16384:    w2    = (const float*)d_in[i]; break;
            case 128:      w3    = (const float*)d_in[i]; break;
            default: break;
        }
    }
    cudaFuncSetAttribute(tcnn_hmma4_kernel,
                         cudaFuncAttributeMaxDynamicSharedMemorySize, SMEM_BYTES);
    tcnn_hmma4_kernel<<<1024, 512, SMEM_BYTES>>>(table, w1, w2, w3, (float*)d_out);
}

// round 12
// speedup vs baseline: 1.1864x; 1.1864x over previous
#include <cuda_runtime.h>
#include <cstdint>

// TCNN_INR via mma.sync tf32 HMMA, warp-specialized persistent CTAs.
// 384 threads: warps 0-7 = MMA (R8 tiling: mg=warp>>2 owns M-tiles mg*4..+4,
// nw=warp&3 owns N-cols nw*32..+32), warps 8-11 = encoding (1 thread/pixel,
// 12 levels) producing tile i+1's E while MMA warps process tile i.
// E double-buffered; H1 relayed in fragment-native layout (STS.128/LDS.128,
// conflict-free). Layer-2 B fragments kt-chunked (2x8) to fit 170-reg budget.

#define PRIME_Y   2654435761u
#define HASH_MASK 0xFFFFFu

__constant__ float    c_scale[12] = {15.0f, 23.0f, 35.0f, 53.0f, 80.0f, 120.5f,
                                     181.25f, 272.375f, 409.0625f, 614.09375f,
                                     921.640625f, 1382.9609375f};
__constant__ unsigned c_res[12]   = {16u, 24u, 36u, 54u, 81u, 122u,
                                     183u, 274u, 411u, 616u, 923u, 1384u};

// k-interleave permutation within 8-groups for E storage: [0,4,1,5,2,6,3,7]
__device__ __forceinline__ int pcol(int k) {
    int j = k & 7;
    return (k & ~7) | ((j < 4) ? (j << 1) : (((j - 4) << 1) | 1));
}

__device__ __forceinline__ uint32_t f2tf32(float f) {
    uint32_t b;
    asm("cvt.rna.tf32.f32 %0, %1;" : "=r"(b) : "f"(f));
    return b;
}

__device__ __forceinline__ void mma8(float& d0, float& d1, float& d2, float& d3,
                                     uint32_t a0, uint32_t a1, uint32_t a2, uint32_t a3,
                                     uint32_t b0, uint32_t b1) {
    asm volatile("mma.sync.aligned.m16n8k8.row.col.f32.tf32.tf32.f32 "
                 "{%0,%1,%2,%3}, {%4,%5,%6,%7}, {%8,%9}, {%0,%1,%2,%3};"
                 : "+f"(d0), "+f"(d1), "+f"(d2), "+f"(d3)
                 : "r"(a0), "r"(a1), "r"(a2), "r"(a3), "r"(b0), "r"(b1));
}

#define BAR_MMA() asm volatile("bar.sync 1, 256;" ::: "memory")

// SMEM float offsets
#define E_STRIDE  50                          // gcd(18,32)=2 -> <=2-way conflicts
#define EBUF      (128 * E_STRIDE)            // 6400 floats per buffer
#define E_OFF     0                           // 2 buffers
#define W1F_OFF   (E_OFF   + 2 * EBUF)        // 12800
#define W2F_OFF   (W1F_OFF + 6144)            // 18944
#define H1F_OFF   (W2F_OFF + 16384)           // 35328
#define P_OFF     (H1F_OFF + 16384)           // 51712
#define W3_OFF    (P_OFF   + 512)             // 52224
#define SMEM_FLOATS (W3_OFF + 128)            // 52352
#define SMEM_BYTES  (SMEM_FLOATS * 4)         // 209408

#define NUM_TILES 8

__global__ void __launch_bounds__(384, 1)
tcnn_hmma5_kernel(const float* __restrict__ table,
                  const float* __restrict__ w1,
                  const float* __restrict__ w2,
                  const float* __restrict__ w3,
                  float* __restrict__ out)
{
    extern __shared__ float sm[];
    float*    E    = sm + E_OFF;
    uint32_t* W1f  = (uint32_t*)(sm + W1F_OFF);
    uint32_t* W2f  = (uint32_t*)(sm + W2F_OFF);
    uint32_t* H1f  = (uint32_t*)(sm + H1F_OFF);
    float*    P    = sm + P_OFF;     // [128 rows][4 nw]
    float*    w3s  = sm + W3_OFF;

    const int tid  = threadIdx.x;
    const int lane = tid & 31;
    const int warp = tid >> 5;
    const int g    = lane >> 2;
    const int t    = lane & 3;
    const bool is_mma = (warp < 8);
    const int mg   = warp >> 2;      // MMA warps: M-group (0..1)
    const int nw   = warp & 3;       // MMA warps: N-slice (0..3)

    // ---- Stage weights ONCE per CTA, in fragment layouts (all 384 threads) ----
    // W1f: idx = ((nw*6+kt)*4+nt)*64 + lane*2 + pair
    // b-pair = (w1[kt*8+t][n], w1[kt*8+t+4][n]) to match E's pcol storage
    #pragma unroll 2
    for (int idx = tid; idx < 6144; idx += 384) {
        int pair = idx & 1;
        int ln   = (idx >> 1) & 31;
        int nt   = (idx >> 6) & 3;
        int kt   = (idx >> 8) % 6;
        int nwi  = idx / 1536;
        int gg = ln >> 2, tt = ln & 3;
        int k = kt * 8 + tt + pair * 4;
        int n = nwi * 32 + nt * 8 + gg;
        W1f[idx] = f2tf32(w1[k * 128 + n]);
    }
    // W2f: idx = ((nw*16+kt)*4+nt)*64 + lane*2 + pair
    // b-pair = (w2[kt*8+2t][n], w2[kt*8+2t+1][n]) to match H1f packing
    #pragma unroll 4
    for (int idx = tid; idx < 16384; idx += 384) {
        int pair = idx & 1;
        int ln   = (idx >> 1) & 31;
        int nt   = (idx >> 6) & 3;
        int kt   = (idx >> 8) & 15;
        int nwi  = idx >> 12;
        int gg = ln >> 2, tt = ln & 3;
        int k = kt * 8 + 2 * tt + pair;
        int n = nwi * 32 + nt * 8 + gg;
        W2f[idx] = f2tf32(w2[k * 128 + n]);
    }
    if (tid < 128) w3s[tid] = w3[tid];
    __syncthreads();

    // ---- Encoding closure: enc warps (8..11), 1 thread/pixel, 12 levels ----
    auto encode_tile = [&](int tile, float* Ebuf) {
        const int   lp  = tid & 127;
        const int   pix = tile * 128 + lp;
        const float fx = (float)(pix & 1023) * (1.0f / 1023.0f);
        const float fy = (float)(pix >> 10)  * (1.0f / 1023.0f);
        uint32_t* Er = (uint32_t*)Ebuf + lp * E_STRIDE;

        #pragma unroll
        for (int l = 0; l < 12; l++) {
            const float    s   = c_scale[l];
            const unsigned res = c_res[l];
            float posx = fmaf(fx, s, 0.5f);
            float posy = fmaf(fy, s, 0.5f);
            float fpx = floorf(posx), fpy = floorf(posy);
            float wx = posx - fpx,    wy = posy - fpy;
            unsigned px0 = (unsigned)fpx, py0 = (unsigned)fpy;
            unsigned px1 = min(px0 + 1u, res - 1u);
            unsigned py1 = min(py0 + 1u, res - 1u);

            unsigned i00, i10, i01, i11;
            if (l < 11) {
                i00 = px0 + py0 * res;  i10 = px1 + py0 * res;
                i01 = px0 + py1 * res;  i11 = px1 + py1 * res;
            } else {
                unsigned hy0 = py0 * PRIME_Y, hy1 = py1 * PRIME_Y;
                i00 = (px0 ^ hy0) & HASH_MASK;  i10 = (px1 ^ hy0) & HASH_MASK;
                i01 = (px0 ^ hy1) & HASH_MASK;  i11 = (px1 ^ hy1) & HASH_MASK;
            }

            const float4* tb = (const float4*)table + ((size_t)l << 20);
            float4 f00 = __ldg(tb + i00);
            float4 f10 = __ldg(tb + i10);
            float4 f01 = __ldg(tb + i01);
            float4 f11 = __ldg(tb + i11);

            float w00 = (1.0f - wx) * (1.0f - wy);
            float w10 = wx * (1.0f - wy);
            float w01 = (1.0f - wx) * wy;
            float w11 = wx * wy;

            int k0 = l * 4;
            Er[pcol(k0 + 0)] = f2tf32(f00.x*w00 + f10.x*w10 + f01.x*w01 + f11.x*w11);
            Er[pcol(k0 + 1)] = f2tf32(f00.y*w00 + f10.y*w10 + f01.y*w01 + f11.y*w11);
            Er[pcol(k0 + 2)] = f2tf32(f00.z*w00 + f10.z*w10 + f01.z*w01 + f11.z*w11);
            Er[pcol(k0 + 3)] = f2tf32(f00.w*w00 + f10.w*w10 + f01.w*w01 + f11.w*w11);
        }
    };

    // ---- Prologue: enc warps fill E[0] for tile 0 ----
    if (!is_mma) encode_tile(blockIdx.x * NUM_TILES, E);
    __syncthreads();

    // ---- Tile loop: MMA warps process tile it; enc warps produce tile it+1 ----
    #pragma unroll 1
    for (int it = 0; it < NUM_TILES; it++) {
        if (!is_mma) {
            if (it + 1 < NUM_TILES)
                encode_tile(blockIdx.x * NUM_TILES + it + 1, E + ((it + 1) & 1) * EBUF);
        } else {
            const float* Eb = E + (it & 1) * EBUF;

            // ---- Layer 1: warp computes H1[mg*64..+64, nw*32..+32) ----
            {
                uint32_t Bf[4][6][2];
                #pragma unroll
                for (int nt = 0; nt < 4; nt++)
                    #pragma unroll
                    for (int kt = 0; kt < 6; kt++) {
                        uint2 v = *(const uint2*)(W1f + (((nw * 6 + kt) * 4 + nt) * 32 + lane) * 2);
                        Bf[nt][kt][0] = v.x;  Bf[nt][kt][1] = v.y;
                    }

                float d[4][4][4];
                #pragma unroll
                for (int mi = 0; mi < 4; mi++)
                    #pragma unroll
                    for (int nt = 0; nt < 4; nt++)
                        d[mi][nt][0] = d[mi][nt][1] = d[mi][nt][2] = d[mi][nt][3] = 0.0f;

                #pragma unroll
                for (int kt = 0; kt < 6; kt++) {
                    #pragma unroll
                    for (int mi = 0; mi < 4; mi++) {
                        int mt = mg * 4 + mi;
                        float2 va = *(const float2*)(Eb + (mt*16 + g    ) * E_STRIDE + kt * 8 + 2 * t);
                        float2 vb = *(const float2*)(Eb + (mt*16 + g + 8) * E_STRIDE + kt * 8 + 2 * t);
                        uint32_t a0 = __float_as_uint(va.x), a1 = __float_as_uint(vb.x);
                        uint32_t a2 = __float_as_uint(va.y), a3 = __float_as_uint(vb.y);
                        #pragma unroll
                        for (int nt = 0; nt < 4; nt++)
                            mma8(d[mi][nt][0], d[mi][nt][1], d[mi][nt][2], d[mi][nt][3],
                                 a0, a1, a2, a3, Bf[nt][kt][0], Bf[nt][kt][1]);
                    }
                }

                // ReLU + tf32 -> H1f, one STS.128 per fragment, (d0,d2,d1,d3).
                #pragma unroll
                for (int mi = 0; mi < 4; mi++) {
                    #pragma unroll
                    for (int nt = 0; nt < 4; nt++) {
                        int mt  = mg * 4 + mi;
                        int ktc = nw * 4 + nt;
                        uint4 v;
                        v.x = f2tf32(fmaxf(d[mi][nt][0], 0.0f));
                        v.y = f2tf32(fmaxf(d[mi][nt][2], 0.0f));
                        v.z = f2tf32(fmaxf(d[mi][nt][1], 0.0f));
                        v.w = f2tf32(fmaxf(d[mi][nt][3], 0.0f));
                        *(uint4*)(H1f + ((mt * 16 + ktc) * 32 + lane) * 4) = v;
                    }
                }
            }
            BAR_MMA();

            // ---- Layer 2 (+w3): warp computes H2[mg*64..+64, nw*32..+32) ----
            {
                float d[4][4][4];
                #pragma unroll
                for (int mi = 0; mi < 4; mi++)
                    #pragma unroll
                    for (int nt = 0; nt < 4; nt++)
                        d[mi][nt][0] = d[mi][nt][1] = d[mi][nt][2] = d[mi][nt][3] = 0.0f;

                // kt-chunked B fragments: 2 chunks of 8 kt (64 live Bf regs)
                #pragma unroll 1
                for (int kc = 0; kc < 2; kc++) {
                    uint32_t Bf[4][8][2];
                    #pragma unroll
                    for (int nt = 0; nt < 4; nt++)
                        #pragma unroll
                        for (int kq = 0; kq < 8; kq++) {
                            int kt = kc * 8 + kq;
                            uint2 v = *(const uint2*)(W2f + (((nw * 16 + kt) * 4 + nt) * 32 + lane) * 2);
                            Bf[nt][kq][0] = v.x;  Bf[nt][kq][1] = v.y;
                        }
                    #pragma unroll
                    for (int kq = 0; kq < 8; kq++) {
                        int kt = kc * 8 + kq;
                        #pragma unroll
                        for (int mi = 0; mi < 4; mi++) {
                            int mt = mg * 4 + mi;
                            uint4 A = *(const uint4*)(H1f + ((mt * 16 + kt) * 32 + lane) * 4);
                            #pragma unroll
                            for (int nt = 0; nt < 4; nt++)
                                mma8(d[mi][nt][0], d[mi][nt][1], d[mi][nt][2], d[mi][nt][3],
                                     A.x, A.y, A.z, A.w, Bf[nt][kq][0], Bf[nt][kq][1]);
                        }
                    }
                }

                // Layer 3 partials over this warp's 32 cols
                float w3c[4][2];
                #pragma unroll
                for (int nt = 0; nt < 4; nt++) {
                    w3c[nt][0] = w3s[nw * 32 + nt * 8 + 2 * t];
                    w3c[nt][1] = w3s[nw * 32 + nt * 8 + 2 * t + 1];
                }
                #pragma unroll
                for (int mi = 0; mi < 4; mi++) {
                    float p0 = 0.0f, p1 = 0.0f;
                    #pragma unroll
                    for (int nt = 0; nt < 4; nt++) {
                        p0 += fmaxf(d[mi][nt][0], 0.0f) * w3c[nt][0]
                            + fmaxf(d[mi][nt][1], 0.0f) * w3c[nt][1];
                        p1 += fmaxf(d[mi][nt][2], 0.0f) * w3c[nt][0]
                            + fmaxf(d[mi][nt][3], 0.0f) * w3c[nt][1];
                    }
                    p0 += __shfl_xor_sync(0xFFFFFFFFu, p0, 1);
                    p0 += __shfl_xor_sync(0xFFFFFFFFu, p0, 2);
                    p1 += __shfl_xor_sync(0xFFFFFFFFu, p1, 1);
                    p1 += __shfl_xor_sync(0xFFFFFFFFu, p1, 2);
                    if (t == 0) {
                        int row0 = mg * 64 + mi * 16 + g;
                        P[(row0    ) * 4 + nw] = p0;
                        P[(row0 + 8) * 4 + nw] = p1;
                    }
                }
            }
            BAR_MMA();

            // ---- Cross-warp reduction + output (threads 0..127 are MMA warps) ----
            if (tid < 128) {
                float4 v = *(const float4*)(P + tid * 4);
                out[(blockIdx.x * NUM_TILES + it) * 128 + tid] = v.x + v.y + v.z + v.w;
            }
        }
        __syncthreads();   // buffer handoff: E[(it+1)&1] ready; H1f/P reusable
    }
}

extern "C" void kernel_launch(void* const* d_in, const int* in_sizes, int n_in,
                              void* d_out, int out_size)
{
    const float *table = nullptr, *w1 = nullptr, *w2 = nullptr, *w3 = nullptr;
    for (int i = 0; i < n_in; i++) {
        switch (in_sizes[i]) {
            case 50331648: table = (const float*)d_in[i]; break;
            case 6144:     w1    = (const float*)d_in[i]; break;
            case 16384:    w2    = (const float*)d_in[i]; break;
            case 128:      w3    = (const float*)d_in[i]; break;
            default: break;
        }
    }
    cudaFuncSetAttribute(tcnn_hmma5_kernel,
                         cudaFuncAttributeMaxDynamicSharedMemorySize, SMEM_BYTES);
    tcnn_hmma5_kernel<<<1024, 384, SMEM_BYTES>>>(table, w1, w2, w3, (float*)d_out);
}

// round 13
// speedup vs baseline: 1.2258x; 1.0332x over previous
#include <cuda_runtime.h>
#include <cstdint>

// TCNN_INR via mma.sync tf32 HMMA, warp-specialized persistent CTAs.
// 512 threads: warps 0-7 = MMA (mg=warp>>2 owns M-tiles mg*4..+4, nw=warp&3
// owns N-cols nw*32..+32 — the traffic-optimal R8 tiling), warps 8-15 = enc
// (2 threads/pixel, 6 levels each) producing tile i+1's E while MMA warps
// process tile i. B fragments kt-chunked (L1: 2x3, L2: 4x4) to fit the
// 128-reg cap at 512 threads. H1 relayed fragment-native (conflict-free
// STS.128/LDS.128 via even/odd neuron permutation).

#define PRIME_Y   2654435761u
#define HASH_MASK 0xFFFFFu

__constant__ float    c_scale[12] = {15.0f, 23.0f, 35.0f, 53.0f, 80.0f, 120.5f,
                                     181.25f, 272.375f, 409.0625f, 614.09375f,
                                     921.640625f, 1382.9609375f};
__constant__ unsigned c_res[12]   = {16u, 24u, 36u, 54u, 81u, 122u,
                                     183u, 274u, 411u, 616u, 923u, 1384u};

// k-interleave permutation within 8-groups for E storage: [0,4,1,5,2,6,3,7]
__device__ __forceinline__ int pcol(int k) {
    int j = k & 7;
    return (k & ~7) | ((j < 4) ? (j << 1) : (((j - 4) << 1) | 1));
}

__device__ __forceinline__ uint32_t f2tf32(float f) {
    uint32_t b;
    asm("cvt.rna.tf32.f32 %0, %1;" : "=r"(b) : "f"(f));
    return b;
}

__device__ __forceinline__ void mma8(float& d0, float& d1, float& d2, float& d3,
                                     uint32_t a0, uint32_t a1, uint32_t a2, uint32_t a3,
                                     uint32_t b0, uint32_t b1) {
    asm volatile("mma.sync.aligned.m16n8k8.row.col.f32.tf32.tf32.f32 "
                 "{%0,%1,%2,%3}, {%4,%5,%6,%7}, {%8,%9}, {%0,%1,%2,%3};"
                 : "+f"(d0), "+f"(d1), "+f"(d2), "+f"(d3)
                 : "r"(a0), "r"(a1), "r"(a2), "r"(a3), "r"(b0), "r"(b1));
}

#define BAR_MMA() asm volatile("bar.sync 1, 256;" ::: "memory")

// SMEM float offsets
#define E_STRIDE  50                          // gcd(18,32)=2 -> <=2-way conflicts
#define EBUF      (128 * E_STRIDE)            // 6400 floats per buffer
#define E_OFF     0                           // 2 buffers
#define W1F_OFF   (E_OFF   + 2 * EBUF)        // 12800
#define W2F_OFF   (W1F_OFF + 6144)            // 18944
#define H1F_OFF   (W2F_OFF + 16384)           // 35328
#define P_OFF     (H1F_OFF + 16384)           // 51712
#define W3_OFF    (P_OFF   + 512)             // 52224
#define SMEM_FLOATS (W3_OFF + 128)            // 52352
#define SMEM_BYTES  (SMEM_FLOATS * 4)         // 209408

#define NUM_TILES 8

__global__ void __launch_bounds__(512, 1)
tcnn_hmma6_kernel(const float* __restrict__ table,
                  const float* __restrict__ w1,
                  const float* __restrict__ w2,
                  const float* __restrict__ w3,
                  float* __restrict__ out)
{
    extern __shared__ float sm[];
    float*    E    = sm + E_OFF;
    uint32_t* W1f  = (uint32_t*)(sm + W1F_OFF);
    uint32_t* W2f  = (uint32_t*)(sm + W2F_OFF);
    uint32_t* H1f  = (uint32_t*)(sm + H1F_OFF);
    float*    P    = sm + P_OFF;     // [128 rows][4 nw]
    float*    w3s  = sm + W3_OFF;

    const int tid  = threadIdx.x;
    const int lane = tid & 31;
    const int warp = tid >> 5;
    const int g    = lane >> 2;
    const int t    = lane & 3;
    const bool is_mma = (warp < 8);
    const int mg   = warp >> 2;      // MMA warps: M-group (0..1)
    const int nw   = warp & 3;       // MMA warps: N-slice (0..3)

    // ---- Stage weights ONCE per CTA, in fragment layouts (all 512 threads) ----
    // W1f: idx = ((nw*6+kt)*4+nt)*64 + lane*2 + pair
    // b-pair = (w1[kt*8+t][n], w1[kt*8+t+4][n]) to match E's pcol storage
    #pragma unroll 2
    for (int idx = tid; idx < 6144; idx += 512) {
        int pair = idx & 1;
        int ln   = (idx >> 1) & 31;
        int nt   = (idx >> 6) & 3;
        int kt   = (idx >> 8) % 6;
        int nwi  = idx / 1536;
        int gg = ln >> 2, tt = ln & 3;
        int k = kt * 8 + tt + pair * 4;
        int n = nwi * 32 + nt * 8 + gg;
        W1f[idx] = f2tf32(w1[k * 128 + n]);
    }
    // W2f: idx = ((nw*16+kt)*4+nt)*64 + lane*2 + pair
    // b-pair = (w2[kt*8+2t][n], w2[kt*8+2t+1][n]) to match H1f packing
    #pragma unroll 4
    for (int idx = tid; idx < 16384; idx += 512) {
        int pair = idx & 1;
        int ln   = (idx >> 1) & 31;
        int nt   = (idx >> 6) & 3;
        int kt   = (idx >> 8) & 15;
        int nwi  = idx >> 12;
        int gg = ln >> 2, tt = ln & 3;
        int k = kt * 8 + 2 * tt + pair;
        int n = nwi * 32 + nt * 8 + gg;
        W2f[idx] = f2tf32(w2[k * 128 + n]);
    }
    if (tid < 128) w3s[tid] = w3[tid];
    __syncthreads();

    // ---- Encoding: enc warps (8..15), 2 threads/pixel, 6 levels each ----
    auto encode_tile = [&](int tile, float* Ebuf) {
        const int   lp    = tid & 127;
        const int   lbase = ((tid >> 7) & 1) * 6;
        const int   pix   = tile * 128 + lp;
        const float fx = (float)(pix & 1023) * (1.0f / 1023.0f);
        const float fy = (float)(pix >> 10)  * (1.0f / 1023.0f);
        uint32_t* Er = (uint32_t*)Ebuf + lp * E_STRIDE;

        #pragma unroll
        for (int li = 0; li < 6; li++) {
            const int      l   = lbase + li;
            const float    s   = c_scale[l];
            const unsigned res = c_res[l];
            float posx = fmaf(fx, s, 0.5f);
            float posy = fmaf(fy, s, 0.5f);
            float fpx = floorf(posx), fpy = floorf(posy);
            float wx = posx - fpx,    wy = posy - fpy;
            unsigned px0 = (unsigned)fpx, py0 = (unsigned)fpy;
            unsigned px1 = min(px0 + 1u, res - 1u);
            unsigned py1 = min(py0 + 1u, res - 1u);

            unsigned i00, i10, i01, i11;
            if (l < 11) {
                i00 = px0 + py0 * res;  i10 = px1 + py0 * res;
                i01 = px0 + py1 * res;  i11 = px1 + py1 * res;
            } else {
                unsigned hy0 = py0 * PRIME_Y, hy1 = py1 * PRIME_Y;
                i00 = (px0 ^ hy0) & HASH_MASK;  i10 = (px1 ^ hy0) & HASH_MASK;
                i01 = (px0 ^ hy1) & HASH_MASK;  i11 = (px1 ^ hy1) & HASH_MASK;
            }

            const float4* tb = (const float4*)table + ((size_t)l << 20);
            float4 f00 = __ldg(tb + i00);
            float4 f10 = __ldg(tb + i10);
            float4 f01 = __ldg(tb + i01);
            float4 f11 = __ldg(tb + i11);

            float w00 = (1.0f - wx) * (1.0f - wy);
            float w10 = wx * (1.0f - wy);
            float w01 = (1.0f - wx) * wy;
            float w11 = wx * wy;

            int k0 = l * 4;
            Er[pcol(k0 + 0)] = f2tf32(f00.x*w00 + f10.x*w10 + f01.x*w01 + f11.x*w11);
            Er[pcol(k0 + 1)] = f2tf32(f00.y*w00 + f10.y*w10 + f01.y*w01 + f11.y*w11);
            Er[pcol(k0 + 2)] = f2tf32(f00.z*w00 + f10.z*w10 + f01.z*w01 + f11.z*w11);
            Er[pcol(k0 + 3)] = f2tf32(f00.w*w00 + f10.w*w10 + f01.w*w01 + f11.w*w11);
        }
    };

    // ---- Prologue: enc warps fill E[0] for tile 0 ----
    if (!is_mma) encode_tile(blockIdx.x * NUM_TILES, E);
    __syncthreads();

    // ---- Tile loop: MMA warps process tile it; enc warps produce tile it+1 ----
    #pragma unroll 1
    for (int it = 0; it < NUM_TILES; it++) {
        if (!is_mma) {
            if (it + 1 < NUM_TILES)
                encode_tile(blockIdx.x * NUM_TILES + it + 1, E + ((it + 1) & 1) * EBUF);
        } else {
            const float* Eb = E + (it & 1) * EBUF;

            // ---- Layer 1: warp computes H1[mg*64..+64, nw*32..+32) ----
            {
                float d[4][4][4];
                #pragma unroll
                for (int mi = 0; mi < 4; mi++)
                    #pragma unroll
                    for (int nt = 0; nt < 4; nt++)
                        d[mi][nt][0] = d[mi][nt][1] = d[mi][nt][2] = d[mi][nt][3] = 0.0f;

                // kt-chunked B fragments: 2 chunks of 3 kt (24 live Bf regs)
                #pragma unroll
                for (int kc = 0; kc < 2; kc++) {
                    uint32_t Bf[4][3][2];
                    #pragma unroll
                    for (int nt = 0; nt < 4; nt++)
                        #pragma unroll
                        for (int kq = 0; kq < 3; kq++) {
                            int kt = kc * 3 + kq;
                            uint2 v = *(const uint2*)(W1f + (((nw * 6 + kt) * 4 + nt) * 32 + lane) * 2);
                            Bf[nt][kq][0] = v.x;  Bf[nt][kq][1] = v.y;
                        }
                    #pragma unroll
                    for (int kq = 0; kq < 3; kq++) {
                        int kt = kc * 3 + kq;
                        #pragma unroll
                        for (int mi = 0; mi < 4; mi++) {
                            int mt = mg * 4 + mi;
                            float2 va = *(const float2*)(Eb + (mt*16 + g    ) * E_STRIDE + kt * 8 + 2 * t);
                            float2 vb = *(const float2*)(Eb + (mt*16 + g + 8) * E_STRIDE + kt * 8 + 2 * t);
                            uint32_t a0 = __float_as_uint(va.x), a1 = __float_as_uint(vb.x);
                            uint32_t a2 = __float_as_uint(va.y), a3 = __float_as_uint(vb.y);
                            #pragma unroll
                            for (int nt = 0; nt < 4; nt++)
                                mma8(d[mi][nt][0], d[mi][nt][1], d[mi][nt][2], d[mi][nt][3],
                                     a0, a1, a2, a3, Bf[nt][kq][0], Bf[nt][kq][1]);
                        }
                    }
                }

                // ReLU + tf32 -> H1f, one STS.128 per fragment, (d0,d2,d1,d3).
                #pragma unroll
                for (int mi = 0; mi < 4; mi++) {
                    #pragma unroll
                    for (int nt = 0; nt < 4; nt++) {
                        int mt  = mg * 4 + mi;
                        int ktc = nw * 4 + nt;
                        uint4 v;
                        v.x = f2tf32(fmaxf(d[mi][nt][0], 0.0f));
                        v.y = f2tf32(fmaxf(d[mi][nt][2], 0.0f));
                        v.z = f2tf32(fmaxf(d[mi][nt][1], 0.0f));
                        v.w = f2tf32(fmaxf(d[mi][nt][3], 0.0f));
                        *(uint4*)(H1f + ((mt * 16 + ktc) * 32 + lane) * 4) = v;
                    }
                }
            }
            BAR_MMA();

            // ---- Layer 2 (+w3): warp computes H2[mg*64..+64, nw*32..+32) ----
            {
                float d[4][4][4];
                #pragma unroll
                for (int mi = 0; mi < 4; mi++)
                    #pragma unroll
                    for (int nt = 0; nt < 4; nt++)
                        d[mi][nt][0] = d[mi][nt][1] = d[mi][nt][2] = d[mi][nt][3] = 0.0f;

                // kt-chunked B fragments: 4 chunks of 4 kt (32 live Bf regs)
                #pragma unroll
                for (int kc = 0; kc < 4; kc++) {
                    uint32_t Bf[4][4][2];
                    #pragma unroll
                    for (int nt = 0; nt < 4; nt++)
                        #pragma unroll
                        for (int kq = 0; kq < 4; kq++) {
                            int kt = kc * 4 + kq;
                            uint2 v = *(const uint2*)(W2f + (((nw * 16 + kt) * 4 + nt) * 32 + lane) * 2);
                            Bf[nt][kq][0] = v.x;  Bf[nt][kq][1] = v.y;
                        }
                    #pragma unroll
                    for (int kq = 0; kq < 4; kq++) {
                        int kt = kc * 4 + kq;
                        #pragma unroll
                        for (int mi = 0; mi < 4; mi++) {
                            int mt = mg * 4 + mi;
                            uint4 A = *(const uint4*)(H1f + ((mt * 16 + kt) * 32 + lane) * 4);
                            #pragma unroll
                            for (int nt = 0; nt < 4; nt++)
                                mma8(d[mi][nt][0], d[mi][nt][1], d[mi][nt][2], d[mi][nt][3],
                                     A.x, A.y, A.z, A.w, Bf[nt][kq][0], Bf[nt][kq][1]);
                        }
                    }
                }

                // Layer 3 partials over this warp's 32 cols
                float w3c[4][2];
                #pragma unroll
                for (int nt = 0; nt < 4; nt++) {
                    w3c[nt][0] = w3s[nw * 32 + nt * 8 + 2 * t];
                    w3c[nt][1] = w3s[nw * 32 + nt * 8 + 2 * t + 1];
                }
                #pragma unroll
                for (int mi = 0; mi < 4; mi++) {
                    float p0 = 0.0f, p1 = 0.0f;
                    #pragma unroll
                    for (int nt = 0; nt < 4; nt++) {
                        p0 += fmaxf(d[mi][nt][0], 0.0f) * w3c[nt][0]
                            + fmaxf(d[mi][nt][1], 0.0f) * w3c[nt][1];
                        p1 += fmaxf(d[mi][nt][2], 0.0f) * w3c[nt][0]
                            + fmaxf(d[mi][nt][3], 0.0f) * w3c[nt][1];
                    }
                    p0 += __shfl_xor_sync(0xFFFFFFFFu, p0, 1);
                    p0 += __shfl_xor_sync(0xFFFFFFFFu, p0, 2);
                    p1 += __shfl_xor_sync(0xFFFFFFFFu, p1, 1);
                    p1 += __shfl_xor_sync(0xFFFFFFFFu, p1, 2);
                    if (t == 0) {
                        int row0 = mg * 64 + mi * 16 + g;
                        P[(row0    ) * 4 + nw] = p0;
                        P[(row0 + 8) * 4 + nw] = p1;
                    }
                }
            }
            BAR_MMA();

            // ---- Cross-warp reduction + output (threads 0..127 are MMA warps) ----
            if (tid < 128) {
                float4 v = *(const float4*)(P + tid * 4);
                out[(blockIdx.x * NUM_TILES + it) * 128 + tid] = v.x + v.y + v.z + v.w;
            }
        }
        __syncthreads();   // buffer handoff: E[(it+1)&1] ready; H1f/P reusable
    }
}

extern "C" void kernel_launch(void* const* d_in, const int* in_sizes, int n_in,
                              void* d_out, int out_size)
{
    const float *table = nullptr, *w1 = nullptr, *w2 = nullptr, *w3 = nullptr;
    for (int i = 0; i < n_in; i++) {
        switch (in_sizes[i]) {
            case 50331648: table = (const float*)d_in[i]; break;
            case 6144:     w1    = (const float*)d_in[i]; break;
            case 16384:    w2    = (const float*)d_in[i]; break;
            case 128:      w3    = (const float*)d_in[i]; break;
            default: break;
        }
    }
    cudaFuncSetAttribute(tcnn_hmma6_kernel,
                         cudaFuncAttributeMaxDynamicSharedMemorySize, SMEM_BYTES);
    tcnn_hmma6_kernel<<<1024, 512, SMEM_BYTES>>>(table, w1, w2, w3, (float*)d_out);
}

// round 14
// speedup vs baseline: 2.0584x; 1.6791x over previous
#include <cuda_runtime.h>
#include <cuda_fp16.h>
#include <cstdint>

// TCNN_INR via mma.sync fp16 m16n8k16 HMMA (fp32 accum), warp-specialized
// persistent CTAs. 512 threads: warps 0-7 MMA (mg x nw = 2x4 tiling, Nw=32),
// warps 8-15 encoding (2 thr/px, 6 levels) double-buffering E for tile i+1.
// Encoding scaled by 2^12 so fp16 stays in normal range; undone at output.
// H1 relayed fragment-native: producer D-quads == consumer A-fragment at the
// same lane (one STS.128/LDS.128, conflict-free).

#define PRIME_Y   2654435761u
#define HASH_MASK 0xFFFFFu
#define ENC_SCALE 4096.0f
#define INV_SCALE (1.0f / 4096.0f)

__constant__ float    c_scale[12] = {15.0f, 23.0f, 35.0f, 53.0f, 80.0f, 120.5f,
                                     181.25f, 272.375f, 409.0625f, 614.09375f,
                                     921.640625f, 1382.9609375f};
__constant__ unsigned c_res[12]   = {16u, 24u, 36u, 54u, 81u, 122u,
                                     183u, 274u, 411u, 616u, 923u, 1384u};

__device__ __forceinline__ uint32_t pack_h2(float lo, float hi) {
    __half2 h = __floats2half2_rn(lo, hi);
    return *(uint32_t*)&h;
}

// half2-unit permutation within 8-unit (16 fp16) k-groups: unit u -> slot
// [0,4,1,5,2,6,3,7] so consumer LDS.64 at 2t gives units (t, t+4).
__device__ __forceinline__ int uslot(int u) {
    return (u < 4) ? (u << 1) : (((u - 4) << 1) | 1);
}

__device__ __forceinline__ void mma16(float& d0, float& d1, float& d2, float& d3,
                                      uint32_t a0, uint32_t a1, uint32_t a2, uint32_t a3,
                                      uint32_t b0, uint32_t b1) {
    asm volatile("mma.sync.aligned.m16n8k16.row.col.f32.f16.f16.f32 "
                 "{%0,%1,%2,%3}, {%4,%5,%6,%7}, {%8,%9}, {%0,%1,%2,%3};"
                 : "+f"(d0), "+f"(d1), "+f"(d2), "+f"(d3)
                 : "r"(a0), "r"(a1), "r"(a2), "r"(a3), "r"(b0), "r"(b1));
}

#define BAR_MMA() asm volatile("bar.sync 1, 256;" ::: "memory")

// SMEM uint32 offsets
#define E_STRIDE  26                          // u32/row (24 data + pad), even for LDS.64
#define EBUF      (128 * E_STRIDE)            // 3328
#define E_OFF     0                           // 2 buffers
#define W1F_OFF   (E_OFF   + 2 * EBUF)        // 6656   (3072 u32)
#define W2F_OFF   (W1F_OFF + 3072)            // 9728   (8192 u32)
#define H1F_OFF   (W2F_OFF + 8192)            // 17920  (8192 u32)
#define P_OFF     (H1F_OFF + 8192)            // 26112  (512 f32)
#define W3_OFF    (P_OFF   + 512)             // 26624  (128 f32)
#define SMEM_U32  (W3_OFF + 128)              // 26752
#define SMEM_BYTES (SMEM_U32 * 4)             // 107008

#define NUM_TILES 8

__global__ void __launch_bounds__(512, 1)
tcnn_hmma7_kernel(const float* __restrict__ table,
                  const float* __restrict__ w1,
                  const float* __restrict__ w2,
                  const float* __restrict__ w3,
                  float* __restrict__ out)
{
    extern __shared__ uint32_t smu[];
    uint32_t* E    = smu + E_OFF;
    uint32_t* W1f  = smu + W1F_OFF;
    uint32_t* W2f  = smu + W2F_OFF;
    uint32_t* H1f  = smu + H1F_OFF;
    float*    P    = (float*)(smu + P_OFF);    // [128 rows][4 nw]
    float*    w3s  = (float*)(smu + W3_OFF);

    const int tid  = threadIdx.x;
    const int lane = tid & 31;
    const int warp = tid >> 5;
    const int g    = lane >> 2;
    const int t    = lane & 3;
    const bool is_mma = (warp < 8);
    const int mg   = warp >> 2;      // MMA warps: M-group (0..1)
    const int nw   = warp & 3;       // MMA warps: N-slice (0..3)

    // ---- Stage weights ONCE per CTA, fp16 fragment layouts ----
    // W1f entry (nwi,kt,nt,lane,pair): pair p holds half2(w1[k][n], w1[k+1][n]),
    // k = kt*16 + 2*tt + p*8, n = nwi*32 + nt*8 + gg.  3 kt-groups (K=48).
    #pragma unroll
    for (int idx = tid; idx < 3072; idx += 512) {
        int pair = idx & 1;
        int ln   = (idx >> 1) & 31;
        int nt   = (idx >> 6) & 3;
        int kt   = (idx >> 8) % 3;
        int nwi  = idx / 768;
        int gg = ln >> 2, tt = ln & 3;
        int k = kt * 16 + 2 * tt + pair * 8;
        int n = nwi * 32 + nt * 8 + gg;
        W1f[idx] = pack_h2(w1[k * 128 + n], w1[(k + 1) * 128 + n]);
    }
    // W2f: same but 8 kt-groups (K=128)
    #pragma unroll
    for (int idx = tid; idx < 8192; idx += 512) {
        int pair = idx & 1;
        int ln   = (idx >> 1) & 31;
        int nt   = (idx >> 6) & 3;
        int kt   = (idx >> 8) & 7;
        int nwi  = idx >> 11;
        int gg = ln >> 2, tt = ln & 3;
        int k = kt * 16 + 2 * tt + pair * 8;
        int n = nwi * 32 + nt * 8 + gg;
        W2f[idx] = pack_h2(w2[k * 128 + n], w2[(k + 1) * 128 + n]);
    }
    if (tid < 128) w3s[tid] = w3[tid];
    __syncthreads();

    // ---- Encoding: enc warps (8..15), 2 threads/pixel, 6 levels each ----
    auto encode_tile = [&](int tile, uint32_t* Ebuf) {
        const int   lp    = tid & 127;
        const int   lbase = ((tid >> 7) & 1) * 6;
        const int   pix   = tile * 128 + lp;
        const float fx = (float)(pix & 1023) * (1.0f / 1023.0f);
        const float fy = (float)(pix >> 10)  * (1.0f / 1023.0f);
        uint32_t* Er = Ebuf + lp * E_STRIDE;

        #pragma unroll
        for (int li = 0; li < 6; li++) {
            const int      l   = lbase + li;
            const float    s   = c_scale[l];
            const unsigned res = c_res[l];
            float posx = fmaf(fx, s, 0.5f);
            float posy = fmaf(fy, s, 0.5f);
            float fpx = floorf(posx), fpy = floorf(posy);
            float wx = posx - fpx,    wy = posy - fpy;
            unsigned px0 = (unsigned)fpx, py0 = (unsigned)fpy;
            unsigned px1 = min(px0 + 1u, res - 1u);
            unsigned py1 = min(py0 + 1u, res - 1u);

            unsigned i00, i10, i01, i11;
            if (l < 11) {
                i00 = px0 + py0 * res;  i10 = px1 + py0 * res;
                i01 = px0 + py1 * res;  i11 = px1 + py1 * res;
            } else {
                unsigned hy0 = py0 * PRIME_Y, hy1 = py1 * PRIME_Y;
                i00 = (px0 ^ hy0) & HASH_MASK;  i10 = (px1 ^ hy0) & HASH_MASK;
                i01 = (px0 ^ hy1) & HASH_MASK;  i11 = (px1 ^ hy1) & HASH_MASK;
            }

            const float4* tb = (const float4*)table + ((size_t)l << 20);
            float4 f00 = __ldg(tb + i00);
            float4 f10 = __ldg(tb + i10);
            float4 f01 = __ldg(tb + i01);
            float4 f11 = __ldg(tb + i11);

            // bilinear weights, scaled by 2^12 for fp16 normal range
            float w00 = (1.0f - wx) * (1.0f - wy) * ENC_SCALE;
            float w10 = wx * (1.0f - wy) * ENC_SCALE;
            float w01 = (1.0f - wx) * wy * ENC_SCALE;
            float w11 = wx * wy * ENC_SCALE;

            float e0 = f00.x*w00 + f10.x*w10 + f01.x*w01 + f11.x*w11;
            float e1 = f00.y*w00 + f10.y*w10 + f01.y*w01 + f11.y*w11;
            float e2 = f00.z*w00 + f10.z*w10 + f01.z*w01 + f11.z*w11;
            float e3 = f00.w*w00 + f10.w*w10 + f01.w*w01 + f11.w*w11;

            // level l -> k = 4l..4l+3 -> half2 units 2l, 2l+1 within group l>>2
            int grp = l >> 2;
            int u0  = (2 * l) & 7;
            Er[grp * 8 + uslot(u0)]     = pack_h2(e0, e1);
            Er[grp * 8 + uslot(u0 + 1)] = pack_h2(e2, e3);
        }
    };

    // ---- Prologue: enc warps fill E[0] for tile 0 ----
    if (!is_mma) encode_tile(blockIdx.x * NUM_TILES, E);
    __syncthreads();

    // ---- Tile loop ----
    #pragma unroll 1
    for (int it = 0; it < NUM_TILES; it++) {
        if (!is_mma) {
            if (it + 1 < NUM_TILES)
                encode_tile(blockIdx.x * NUM_TILES + it + 1, E + ((it + 1) & 1) * EBUF);
        } else {
            const uint32_t* Eb = E + (it & 1) * EBUF;

            // ---- Layer 1: warp computes H1[mg*64..+64, nw*32..+32), K=48 ----
            {
                uint32_t Bf[4][3][2];
                #pragma unroll
                for (int nt = 0; nt < 4; nt++)
                    #pragma unroll
                    for (int kt = 0; kt < 3; kt++) {
                        uint2 v = *(const uint2*)(W1f + (((nw * 3 + kt) * 4 + nt) * 32 + lane) * 2);
                        Bf[nt][kt][0] = v.x;  Bf[nt][kt][1] = v.y;
                    }

                float d[4][4][4];
                #pragma unroll
                for (int mi = 0; mi < 4; mi++)
                    #pragma unroll
                    for (int nt = 0; nt < 4; nt++)
                        d[mi][nt][0] = d[mi][nt][1] = d[mi][nt][2] = d[mi][nt][3] = 0.0f;

                #pragma unroll
                for (int kt = 0; kt < 3; kt++) {
                    #pragma unroll
                    for (int mi = 0; mi < 4; mi++) {
                        int mt = mg * 4 + mi;
                        uint2 ua = *(const uint2*)(Eb + (mt*16 + g    ) * E_STRIDE + kt * 8 + 2 * t);
                        uint2 ub = *(const uint2*)(Eb + (mt*16 + g + 8) * E_STRIDE + kt * 8 + 2 * t);
                        #pragma unroll
                        for (int nt = 0; nt < 4; nt++)
                            mma16(d[mi][nt][0], d[mi][nt][1], d[mi][nt][2], d[mi][nt][3],
                                  ua.x, ub.x, ua.y, ub.y, Bf[nt][kt][0], Bf[nt][kt][1]);
                    }
                }

                // ReLU -> fp16 -> H1f. Producer (nt=2j,2j+1) quads == consumer
                // a0..a3 at the same lane for k-group ktc = nw*2 + j.
                #pragma unroll
                for (int mi = 0; mi < 4; mi++) {
                    #pragma unroll
                    for (int j = 0; j < 2; j++) {
                        int mt  = mg * 4 + mi;
                        int ktc = nw * 2 + j;
                        uint4 v;
                        v.x = pack_h2(fmaxf(d[mi][2*j  ][0], 0.0f), fmaxf(d[mi][2*j  ][1], 0.0f));
                        v.y = pack_h2(fmaxf(d[mi][2*j  ][2], 0.0f), fmaxf(d[mi][2*j  ][3], 0.0f));
                        v.z = pack_h2(fmaxf(d[mi][2*j+1][0], 0.0f), fmaxf(d[mi][2*j+1][1], 0.0f));
                        v.w = pack_h2(fmaxf(d[mi][2*j+1][2], 0.0f), fmaxf(d[mi][2*j+1][3], 0.0f));
                        *(uint4*)(H1f + ((mt * 8 + ktc) * 32 + lane) * 4) = v;
                    }
                }
            }
            BAR_MMA();

            // ---- Layer 2 (+w3): warp computes H2[mg*64..+64, nw*32..+32), K=128 ----
            {
                float d[4][4][4];
                #pragma unroll
                for (int mi = 0; mi < 4; mi++)
                    #pragma unroll
                    for (int nt = 0; nt < 4; nt++)
                        d[mi][nt][0] = d[mi][nt][1] = d[mi][nt][2] = d[mi][nt][3] = 0.0f;

                // kt-chunked B fragments: 2 chunks of 4 kt (32 live Bf regs)
                #pragma unroll
                for (int kc = 0; kc < 2; kc++) {
                    uint32_t Bf[4][4][2];
                    #pragma unroll
                    for (int nt = 0; nt < 4; nt++)
                        #pragma unroll
                        for (int kq = 0; kq < 4; kq++) {
                            int kt = kc * 4 + kq;
                            uint2 v = *(const uint2*)(W2f + (((nw * 8 + kt) * 4 + nt) * 32 + lane) * 2);
                            Bf[nt][kq][0] = v.x;  Bf[nt][kq][1] = v.y;
                        }
                    #pragma unroll
                    for (int kq = 0; kq < 4; kq++) {
                        int kt = kc * 4 + kq;
                        #pragma unroll
                        for (int mi = 0; mi < 4; mi++) {
                            int mt = mg * 4 + mi;
                            uint4 A = *(const uint4*)(H1f + ((mt * 8 + kt) * 32 + lane) * 4);
                            #pragma unroll
                            for (int nt = 0; nt < 4; nt++)
                                mma16(d[mi][nt][0], d[mi][nt][1], d[mi][nt][2], d[mi][nt][3],
                                      A.x, A.y, A.z, A.w, Bf[nt][kq][0], Bf[nt][kq][1]);
                        }
                    }
                }

                // Layer 3 partials over this warp's 32 cols
                float w3c[4][2];
                #pragma unroll
                for (int nt = 0; nt < 4; nt++) {
                    w3c[nt][0] = w3s[nw * 32 + nt * 8 + 2 * t];
                    w3c[nt][1] = w3s[nw * 32 + nt * 8 + 2 * t + 1];
                }
                #pragma unroll
                for (int mi = 0; mi < 4; mi++) {
                    float p0 = 0.0f, p1 = 0.0f;
                    #pragma unroll
                    for (int nt = 0; nt < 4; nt++) {
                        p0 += fmaxf(d[mi][nt][0], 0.0f) * w3c[nt][0]
                            + fmaxf(d[mi][nt][1], 0.0f) * w3c[nt][1];
                        p1 += fmaxf(d[mi][nt][2], 0.0f) * w3c[nt][0]
                            + fmaxf(d[mi][nt][3], 0.0f) * w3c[nt][1];
                    }
                    p0 += __shfl_xor_sync(0xFFFFFFFFu, p0, 1);
                    p0 += __shfl_xor_sync(0xFFFFFFFFu, p0, 2);
                    p1 += __shfl_xor_sync(0xFFFFFFFFu, p1, 1);
                    p1 += __shfl_xor_sync(0xFFFFFFFFu, p1, 2);
                    if (t == 0) {
                        int row0 = mg * 64 + mi * 16 + g;
                        P[(row0    ) * 4 + nw] = p0;
                        P[(row0 + 8) * 4 + nw] = p1;
                    }
                }
            }
            BAR_MMA();

            // ---- Cross-warp reduction + output (undo 2^12 encoding scale) ----
            if (tid < 128) {
                float4 v = *(const float4*)(P + tid * 4);
                out[(blockIdx.x * NUM_TILES + it) * 128 + tid] =
                    (v.x + v.y + v.z + v.w) * INV_SCALE;
            }
        }
        __syncthreads();   // buffer handoff
    }
}

extern "C" void kernel_launch(void* const* d_in, const int* in_sizes, int n_in,
                              void* d_out, int out_size)
{
    const float *table = nullptr, *w1 = nullptr, *w2 = nullptr, *w3 = nullptr;
    for (int i = 0; i < n_in; i++) {
        switch (in_sizes[i]) {
            case 50331648: table = (const float*)d_in[i]; break;
            case 6144:     w1    = (const float*)d_in[i]; break;
            case 16384:    w2    = (const float*)d_in[i]; break;
            case 128:      w3    = (const float*)d_in[i]; break;
            default: break;
        }
    }
    cudaFuncSetAttribute(tcnn_hmma7_kernel,
                         cudaFuncAttributeMaxDynamicSharedMemorySize, SMEM_BYTES);
    tcnn_hmma7_kernel<<<1024, 512, SMEM_BYTES>>>(table, w1, w2, w3, (float*)d_out);
}